// round 1
// baseline (speedup 1.0000x reference)
#include <cuda_runtime.h>

// Problem constants (fixed by the reference setup)
#define NBATCH 32
#define NATOM 256
#define PAIRS_PB 15360
#define NN (NBATCH * PAIRS_PB)      // 491520 total pairs
#define TOTNATOM (NBATCH * NATOM)   // 8192
#define NWAVE 8
#define NO 13                       // angular channels 1+3+9
#define NORBIT 128
#define SVEC (NO * NWAVE / 4)       // 26 float4 per atom (104 floats)

// Segment-sum scratch: sum_worbital[atom][c][w], stored as float4 (16B aligned).
__device__ float4 g_S[TOTNATOM * SVEC];   // 8192 * 26 * 16B = 3.4 MB

// ---------------------------------------------------------------------------
// Kernel 1: zero the scratch (must happen every launch; graph replays reuse it)
// ---------------------------------------------------------------------------
__global__ void zero_S_kernel() {
    int idx = blockIdx.x * blockDim.x + threadIdx.x;
    if (idx < TOTNATOM * SVEC) g_S[idx] = make_float4(0.f, 0.f, 0.f, 0.f);
}

// ---------------------------------------------------------------------------
// Kernel 2: per-pair compute + vector-RED scatter into g_S
// ---------------------------------------------------------------------------
__device__ __forceinline__ void red_add_v4(float4* ptr, float a, float b, float c, float d) {
    asm volatile("red.global.add.v4.f32 [%0], {%1, %2, %3, %4};"
                 :: "l"(ptr), "f"(a), "f"(b), "f"(c), "f"(d) : "memory");
}

__global__ void __launch_bounds__(256) pair_kernel(
    const float* __restrict__ cart,        // (totnatom, 3)
    const int*   __restrict__ species,     // (totnatom,)
    const int*   __restrict__ atom_index,  // (2, NN) flattened
    const float* __restrict__ shifts,      // (NN, 3)
    const float* __restrict__ rs,          // (NTYPE, 8)
    const float* __restrict__ inta,        // (NTYPE, 8)
    const float* __restrict__ params)      // (NTYPE, 8)
{
    int p = blockIdx.x * blockDim.x + threadIdx.x;
    if (p >= NN) return;

    int b = p / PAIRS_PB;
    int i = atom_index[p]      + b * NATOM;   // center (segment target)
    int j = atom_index[NN + p] + b * NATOM;   // neighbor

    float dx = __ldg(&cart[3 * i + 0]) - __ldg(&cart[3 * j + 0]) + __ldg(&shifts[3 * p + 0]);
    float dy = __ldg(&cart[3 * i + 1]) - __ldg(&cart[3 * j + 1]) + __ldg(&shifts[3 * p + 1]);
    float dz = __ldg(&cart[3 * i + 2]) - __ldg(&cart[3 * j + 2]) + __ldg(&shifts[3 * p + 2]);

    float d2  = dx * dx + dy * dy + dz * dz;
    float inv = rsqrtf(d2);
    float d   = d2 * inv;                 // |r|
    float ux = dx * inv, uy = dy * inv, uz = dz * inv;

    int sp = __ldg(&species[j]) * NWAVE;

    // radial[w] * orbital coefficient (both keyed on neighbor species)
    float rc[NWAVE];
#pragma unroll
    for (int w = 0; w < NWAVE; w++) {
        float t = d - __ldg(&rs[sp + w]);
        rc[w] = __expf(__ldg(&inta[sp + w]) * t * t) * __ldg(&params[sp + w]);
    }

    // angular channels: [1, u, u⊗u (row-major 3x3)]
    float ang[NO] = {1.f,
                     ux, uy, uz,
                     ux * ux, ux * uy, ux * uz,
                     uy * ux, uy * uy, uy * uz,
                     uz * ux, uz * uy, uz * uz};

    float4* Sa = g_S + (size_t)i * SVEC;
#pragma unroll
    for (int c = 0; c < NO; c++) {
        float a = ang[c];
        red_add_v4(&Sa[2 * c + 0], a * rc[0], a * rc[1], a * rc[2], a * rc[3]);
        red_add_v4(&Sa[2 * c + 1], a * rc[4], a * rc[5], a * rc[6], a * rc[7]);
    }
}

// ---------------------------------------------------------------------------
// Kernel 3: per-atom hyper contraction + squared reduction over channels
//   density[a][m] = sum_c ( sum_w S[a][c][w] * hyper[kp(c)][w][m] )^2
// One block per atom, one thread per orbit column m.
// ---------------------------------------------------------------------------
__global__ void __launch_bounds__(NORBIT) density_kernel(
    const float* __restrict__ hyper,   // (3, 8, 128)
    float* __restrict__ out)           // (totnatom, 128)
{
    int a = blockIdx.x;
    int m = threadIdx.x;

    __shared__ float S[NO * NWAVE];
    const float* Sa = (const float*)(g_S + (size_t)a * SVEC);
    if (m < NO * NWAVE) S[m] = Sa[m];
    __syncthreads();

    // per-thread slice of hyper: h[k][w] = hyper[k][w][m]  (coalesced, L2-hot)
    float h[3][NWAVE];
#pragma unroll
    for (int k = 0; k < 3; k++)
#pragma unroll
        for (int w = 0; w < NWAVE; w++)
            h[k][w] = __ldg(&hyper[(k * NWAVE + w) * NORBIT + m]);

    float dens = 0.f;
#pragma unroll
    for (int c = 0; c < NO; c++) {
        const int k = (c == 0) ? 0 : ((c < 4) ? 1 : 2);   // index_para
        float acc = 0.f;
#pragma unroll
        for (int w = 0; w < NWAVE; w++)
            acc += S[c * NWAVE + w] * h[k][w];
        dens += acc * acc;
    }
    out[a * NORBIT + m] = dens;
}

// ---------------------------------------------------------------------------
// Launch
// ---------------------------------------------------------------------------
extern "C" void kernel_launch(void* const* d_in, const int* in_sizes, int n_in,
                              void* d_out, int out_size) {
    const float* cart       = (const float*)d_in[0];
    // d_in[1] = numatoms (unused by the reference math)
    const int*   species    = (const int*)  d_in[2];
    const int*   atom_index = (const int*)  d_in[3];
    const float* shifts     = (const float*)d_in[4];
    const float* rs         = (const float*)d_in[5];
    const float* inta       = (const float*)d_in[6];
    const float* params     = (const float*)d_in[7];
    const float* hyper      = (const float*)d_in[8];
    float* out = (float*)d_out;

    zero_S_kernel<<<(TOTNATOM * SVEC + 255) / 256, 256>>>();
    pair_kernel<<<(NN + 255) / 256, 256>>>(cart, species, atom_index, shifts,
                                           rs, inta, params);
    density_kernel<<<TOTNATOM, NORBIT>>>(hyper, out);
}

// round 2
// speedup vs baseline: 2.0028x; 2.0028x over previous
#include <cuda_runtime.h>

// Problem constants (fixed by the reference setup)
#define NBATCH 32
#define NATOM 256
#define PAIRS_PB 15360
#define NN (NBATCH * PAIRS_PB)      // 491520 total pairs
#define TOTNATOM (NBATCH * NATOM)   // 8192
#define NWAVE 8
#define NO 13                       // angular channels 1+3+9
#define NORBIT 128
#define CAP 96                      // bin capacity (mean 60, sigma 7.7)
#define ATOMS_PER_BLK 16

// Per-atom pair bins: record = {ux,uy,uz,pad, rc0..3, rc4..7} = 3 float4 (48 B)
__device__ float4 g_rec[(size_t)TOTNATOM * CAP * 3];   // ~37.7 MB (L2-resident)
__device__ int    g_cnt[TOTNATOM];
// Overflow fallback accumulator (exact-correctness safety net), layout [atom][c][w]
__device__ float4 g_S[TOTNATOM * (NO * NWAVE / 4)];    // 3.4 MB

// ---------------------------------------------------------------------------
// Kernel 1: zero counters + overflow accumulator
// ---------------------------------------------------------------------------
__global__ void zero_kernel() {
    int idx = blockIdx.x * blockDim.x + threadIdx.x;
    if (idx < TOTNATOM * (NO * NWAVE / 4)) g_S[idx] = make_float4(0.f, 0.f, 0.f, 0.f);
    if (idx < TOTNATOM) g_cnt[idx] = 0;
}

// ---------------------------------------------------------------------------
// Kernel 2: per-pair compute + binning (1 int atomic + 3 STG.128 per pair)
// ---------------------------------------------------------------------------
__device__ __forceinline__ void red_add_v4(float4* ptr, float a, float b, float c, float d) {
    asm volatile("red.global.add.v4.f32 [%0], {%1, %2, %3, %4};"
                 :: "l"(ptr), "f"(a), "f"(b), "f"(c), "f"(d) : "memory");
}

__global__ void __launch_bounds__(256) pair_kernel(
    const float* __restrict__ cart,        // (totnatom, 3)
    const int*   __restrict__ species,     // (totnatom,)
    const int*   __restrict__ atom_index,  // (2, NN) flattened
    const float* __restrict__ shifts,      // (NN, 3)
    const float* __restrict__ rs,          // (NTYPE, 8)
    const float* __restrict__ inta,        // (NTYPE, 8)
    const float* __restrict__ params)      // (NTYPE, 8)
{
    int p = blockIdx.x * blockDim.x + threadIdx.x;
    if (p >= NN) return;

    int b = p / PAIRS_PB;
    int i = atom_index[p]      + b * NATOM;   // center (segment target)
    int j = atom_index[NN + p] + b * NATOM;   // neighbor

    float dx = __ldg(&cart[3 * i + 0]) - __ldg(&cart[3 * j + 0]) + __ldg(&shifts[3 * p + 0]);
    float dy = __ldg(&cart[3 * i + 1]) - __ldg(&cart[3 * j + 1]) + __ldg(&shifts[3 * p + 1]);
    float dz = __ldg(&cart[3 * i + 2]) - __ldg(&cart[3 * j + 2]) + __ldg(&shifts[3 * p + 2]);

    float d2  = dx * dx + dy * dy + dz * dz;
    float inv = rsqrtf(d2);
    float d   = d2 * inv;                 // |r|
    float ux = dx * inv, uy = dy * inv, uz = dz * inv;

    int sp = __ldg(&species[j]) * NWAVE;

    float rc[NWAVE];
#pragma unroll
    for (int w = 0; w < NWAVE; w++) {
        float t = d - __ldg(&rs[sp + w]);
        rc[w] = __expf(__ldg(&inta[sp + w]) * t * t) * __ldg(&params[sp + w]);
    }

    int slot = atomicAdd(&g_cnt[i], 1);
    if (slot < CAP) {
        float4* r = g_rec + ((size_t)i * CAP + slot) * 3;
        r[0] = make_float4(ux, uy, uz, 0.f);
        r[1] = make_float4(rc[0], rc[1], rc[2], rc[3]);
        r[2] = make_float4(rc[4], rc[5], rc[6], rc[7]);
    } else {
        // Overflow fallback: exact red-atomic scatter (expected never taken)
        float ang[NO] = {1.f,
                         ux, uy, uz,
                         ux * ux, ux * uy, ux * uz,
                         uy * ux, uy * uy, uy * uz,
                         uz * ux, uz * uy, uz * uz};
        float4* Sa = g_S + (size_t)i * (NO * NWAVE / 4);
#pragma unroll
        for (int c = 0; c < NO; c++) {
            float a = ang[c];
            red_add_v4(&Sa[2 * c + 0], a * rc[0], a * rc[1], a * rc[2], a * rc[3]);
            red_add_v4(&Sa[2 * c + 1], a * rc[4], a * rc[5], a * rc[6], a * rc[7]);
        }
    }
}

// ---------------------------------------------------------------------------
// Kernel 3: gather (no atomics) + fused hyper contraction + squared reduce.
// 16 atoms/block, 128 threads. Phase 1: 8 threads per atom, thread owns w,
// accumulates S[c][w] over that atom's pair bin. Phase 2: S -> smem.
// Phase 3: thread owns orbit column m, loops 16 atoms.
// ---------------------------------------------------------------------------
__global__ void __launch_bounds__(128) gather_kernel(
    const float* __restrict__ hyper,   // (3, 8, 128)
    float* __restrict__ out)           // (totnatom, 128)
{
    const int tid = threadIdx.x;
    const int la  = tid >> 3;          // local atom 0..15
    const int w   = tid & 7;           // wave index 0..7
    const int a   = blockIdx.x * ATOMS_PER_BLK + la;

    __shared__ float Ssm[ATOMS_PER_BLK * NO * NWAVE];   // 6.5 KB

    // ---- Phase 1: per-(atom, w) moment accumulation over the pair bin ----
    float acc[NO];
    {
        const float* gs = (const float*)(g_S + (size_t)a * (NO * NWAVE / 4));
#pragma unroll
        for (int c = 0; c < NO; c++) acc[c] = gs[c * NWAVE + w];  // overflow init (usually 0)
    }

    const int n = min(g_cnt[a], CAP);
    const float4* rec = g_rec + (size_t)a * CAP * 3;
    const float*  recf = (const float*)rec;

#pragma unroll 4
    for (int p = 0; p < n; p++) {
        float4 u = __ldg(&rec[p * 3]);              // broadcast across 8 threads
        float  r = __ldg(&recf[p * 12 + 4 + w]);    // rc[w]
        acc[0] += r;
        float tx = r * u.x, ty = r * u.y, tz = r * u.z;
        acc[1] += tx;  acc[2] += ty;  acc[3] += tz;
        acc[4]  += tx * u.x;  acc[5]  += tx * u.y;  acc[6]  += tx * u.z;
        acc[7]  += ty * u.x;  acc[8]  += ty * u.y;  acc[9]  += ty * u.z;
        acc[10] += tz * u.x;  acc[11] += tz * u.y;  acc[12] += tz * u.z;
    }

    // ---- Phase 2: stash S into shared (conflict-free: banks la*8 + w) ----
#pragma unroll
    for (int c = 0; c < NO; c++)
        Ssm[la * (NO * NWAVE) + c * NWAVE + w] = acc[c];
    __syncthreads();

    // ---- Phase 3: hyper contraction; thread = orbit column m ----
    const int m = tid;
    float h[3][NWAVE];
#pragma unroll
    for (int k = 0; k < 3; k++)
#pragma unroll
        for (int v = 0; v < NWAVE; v++)
            h[k][v] = __ldg(&hyper[(k * NWAVE + v) * NORBIT + m]);

#pragma unroll 1
    for (int la2 = 0; la2 < ATOMS_PER_BLK; la2++) {
        const float* S = Ssm + la2 * (NO * NWAVE);
        float dens = 0.f;
#pragma unroll
        for (int c = 0; c < NO; c++) {
            const int k = (c == 0) ? 0 : ((c < 4) ? 1 : 2);   // index_para
            float4 s0 = *(const float4*)(S + c * NWAVE);
            float4 s1 = *(const float4*)(S + c * NWAVE + 4);
            float t = s0.x * h[k][0] + s0.y * h[k][1] + s0.z * h[k][2] + s0.w * h[k][3]
                    + s1.x * h[k][4] + s1.y * h[k][5] + s1.z * h[k][6] + s1.w * h[k][7];
            dens += t * t;
        }
        out[(blockIdx.x * ATOMS_PER_BLK + la2) * NORBIT + m] = dens;
    }
}

// ---------------------------------------------------------------------------
// Launch
// ---------------------------------------------------------------------------
extern "C" void kernel_launch(void* const* d_in, const int* in_sizes, int n_in,
                              void* d_out, int out_size) {
    const float* cart       = (const float*)d_in[0];
    // d_in[1] = numatoms (unused by the reference math)
    const int*   species    = (const int*)  d_in[2];
    const int*   atom_index = (const int*)  d_in[3];
    const float* shifts     = (const float*)d_in[4];
    const float* rs         = (const float*)d_in[5];
    const float* inta       = (const float*)d_in[6];
    const float* params     = (const float*)d_in[7];
    const float* hyper      = (const float*)d_in[8];
    float* out = (float*)d_out;

    const int nz = TOTNATOM * (NO * NWAVE / 4);
    zero_kernel<<<(nz + 255) / 256, 256>>>();
    pair_kernel<<<(NN + 255) / 256, 256>>>(cart, species, atom_index, shifts,
                                           rs, inta, params);
    gather_kernel<<<TOTNATOM / ATOMS_PER_BLK, 128>>>(hyper, out);
}

// round 3
// speedup vs baseline: 2.5919x; 1.2941x over previous
#include <cuda_runtime.h>

// Problem constants (fixed by the reference setup)
#define NBATCH 32
#define NATOM 256
#define PAIRS_PB 15360
#define NN (NBATCH * PAIRS_PB)      // 491520 total pairs
#define TOTNATOM (NBATCH * NATOM)   // 8192
#define NWAVE 8
#define NSYM 10                     // symmetric channels: 1, x,y,z, xx,xy,xz,yy,yz,zz
#define NORBIT 128
#define CAP 96                      // bin capacity (mean 60, sigma 7.7)
#define ATOMS_PER_BLK 16
#define SSTRIDE 88                  // smem stride per atom (80 used + 8 pad, bank-clean)

// Per-atom pair bins: record = {ux|sp(2 low bits), uy, uz, d} = 1 float4 (16 B)
__device__ float4 g_rec[(size_t)TOTNATOM * CAP];       // 12.6 MB (L2-resident)
__device__ int    g_cnt[TOTNATOM];                     // zero-init (.bss); gather resets
// Overflow fallback accumulator [atom][c(10)][w(8)] as float4; gather re-zeroes on use
__device__ float4 g_S[TOTNATOM * (NSYM * NWAVE / 4)];  // 2.6 MB

__device__ __forceinline__ void red_add_v4(float4* ptr, float a, float b, float c, float d) {
    asm volatile("red.global.add.v4.f32 [%0], {%1, %2, %3, %4};"
                 :: "l"(ptr), "f"(a), "f"(b), "f"(c), "f"(d) : "memory");
}
__device__ __forceinline__ float ex2_approx(float x) {
    float r;
    asm("ex2.approx.f32 %0, %1;" : "=f"(r) : "f"(x));
    return r;
}

// ---------------------------------------------------------------------------
// Kernel 1: per-pair geometry + binning (1 int atomic + 1 STG.128 per pair)
// ---------------------------------------------------------------------------
__global__ void __launch_bounds__(256) pair_kernel(
    const float* __restrict__ cart,        // (totnatom, 3)
    const int*   __restrict__ species,     // (totnatom,)
    const int*   __restrict__ atom_index,  // (2, NN) flattened
    const float* __restrict__ shifts,      // (NN, 3)
    const float* __restrict__ rs,          // (NTYPE, 8)
    const float* __restrict__ inta,        // (NTYPE, 8)
    const float* __restrict__ params)      // (NTYPE, 8)
{
    int p = blockIdx.x * blockDim.x + threadIdx.x;
    if (p >= NN) return;

    int b = p / PAIRS_PB;
    int i = atom_index[p]      + b * NATOM;   // center (segment target)
    int j = atom_index[NN + p] + b * NATOM;   // neighbor

    float dx = __ldg(&cart[3 * i + 0]) - __ldg(&cart[3 * j + 0]) + __ldg(&shifts[3 * p + 0]);
    float dy = __ldg(&cart[3 * i + 1]) - __ldg(&cart[3 * j + 1]) + __ldg(&shifts[3 * p + 1]);
    float dz = __ldg(&cart[3 * i + 2]) - __ldg(&cart[3 * j + 2]) + __ldg(&shifts[3 * p + 2]);

    float d2  = dx * dx + dy * dy + dz * dz;
    float inv = rsqrtf(d2);
    float d   = d2 * inv;                 // |r|
    float ux = dx * inv, uy = dy * inv, uz = dz * inv;

    int sp = __ldg(&species[j]);

    int slot = atomicAdd(&g_cnt[i], 1);
    if (slot < CAP) {
        // pack species into 2 low mantissa bits of ux (<=3 ulp perturbation)
        unsigned uxb = (__float_as_uint(ux) & ~3u) | (unsigned)sp;
        g_rec[(size_t)i * CAP + slot] = make_float4(__uint_as_float(uxb), uy, uz, d);
    } else {
        // Overflow fallback (expected never taken): exact red-atomic scatter
        float rc[NWAVE];
#pragma unroll
        for (int w = 0; w < NWAVE; w++) {
            float t = d - __ldg(&rs[sp * NWAVE + w]);
            rc[w] = __expf(__ldg(&inta[sp * NWAVE + w]) * t * t) * __ldg(&params[sp * NWAVE + w]);
        }
        float ang[NSYM] = {1.f, ux, uy, uz,
                           ux * ux, ux * uy, ux * uz, uy * uy, uy * uz, uz * uz};
        float4* Sa = g_S + (size_t)i * (NSYM * NWAVE / 4);
#pragma unroll
        for (int c = 0; c < NSYM; c++) {
            float a = ang[c];
            red_add_v4(&Sa[2 * c + 0], a * rc[0], a * rc[1], a * rc[2], a * rc[3]);
            red_add_v4(&Sa[2 * c + 1], a * rc[4], a * rc[5], a * rc[6], a * rc[7]);
        }
    }
}

// ---------------------------------------------------------------------------
// Kernel 2: gather (radial eval fused) + hyper contraction + squared reduce.
// 16 atoms/block, 128 threads. Phase 1: 8 threads/atom (thread owns w),
// accumulates sym moments over the atom's bin. Phase 2: S -> smem.
// Phase 3: thread owns orbit column m, loops 16 atoms.
// Also resets g_cnt (and g_S if overflow) for the next graph replay.
// ---------------------------------------------------------------------------
__global__ void __launch_bounds__(128) gather_kernel(
    const float* __restrict__ rs,      // (NTYPE, 8)
    const float* __restrict__ inta,    // (NTYPE, 8)
    const float* __restrict__ params,  // (NTYPE, 8)
    const float* __restrict__ hyper,   // (3, 8, 128)
    float* __restrict__ out)           // (totnatom, 128)
{
    const int tid = threadIdx.x;
    const int la  = tid >> 3;          // local atom 0..15
    const int w   = tid & 7;           // wave index 0..7
    const int a   = blockIdx.x * ATOMS_PER_BLK + la;

    __shared__ float Trs[32], TA[32], TP[32];                 // species tables
    __shared__ float Ssm[ATOMS_PER_BLK * SSTRIDE];            // 5.6 KB

    if (tid < 32) {
        Trs[tid] = __ldg(&rs[tid]);
        TA[tid]  = __ldg(&inta[tid]) * 1.4426950408889634f;   // fold log2(e)
        TP[tid]  = __ldg(&params[tid]);
    }
    __syncthreads();

    // ---- Phase 1: per-(atom, w) symmetric moment accumulation ----
    const int n  = g_cnt[a];
    const int nc = min(n, CAP);
    if (w == 0) g_cnt[a] = 0;          // reset for next replay (after warp's read)

    float acc[NSYM];
    if (n > CAP) {                     // overflow init + re-zero (expected never)
        float* gs = (float*)(g_S + (size_t)a * (NSYM * NWAVE / 4));
#pragma unroll
        for (int c = 0; c < NSYM; c++) {
            acc[c] = gs[c * NWAVE + w];
            gs[c * NWAVE + w] = 0.f;
        }
    } else {
#pragma unroll
        for (int c = 0; c < NSYM; c++) acc[c] = 0.f;
    }

    const float4* rec = g_rec + (size_t)a * CAP;
#pragma unroll 4
    for (int p = 0; p < nc; p++) {
        float4 r = __ldg(&rec[p]);                 // broadcast across the 8 w-threads
        unsigned uxb = __float_as_uint(r.x);
        int sp8 = (int)(uxb & 3u) * NWAVE + w;
        float ux = __uint_as_float(uxb & ~3u);
        float t  = r.w - Trs[sp8];
        float rc = ex2_approx(TA[sp8] * t * t) * TP[sp8];

        acc[0] += rc;
        float tx = rc * ux, ty = rc * r.y, tz = rc * r.z;
        acc[1] += tx;       acc[2] += ty;       acc[3] += tz;
        acc[4] += tx * ux;  acc[5] += tx * r.y; acc[6] += tx * r.z;
        acc[7] += ty * r.y; acc[8] += ty * r.z; acc[9] += tz * r.z;
    }

    // ---- Phase 2: stash S into shared ----
#pragma unroll
    for (int c = 0; c < NSYM; c++)
        Ssm[la * SSTRIDE + c * NWAVE + w] = acc[c];
    __syncthreads();

    // ---- Phase 3: hyper contraction; thread = orbit column m ----
    const int m = tid;
    float h[3][NWAVE];
#pragma unroll
    for (int k = 0; k < 3; k++)
#pragma unroll
        for (int v = 0; v < NWAVE; v++)
            h[k][v] = __ldg(&hyper[(k * NWAVE + v) * NORBIT + m]);

    const int   k_of[NSYM] = {0, 1, 1, 1, 2, 2, 2, 2, 2, 2};
    const float wt_of[NSYM] = {1.f, 1.f, 1.f, 1.f, 1.f, 2.f, 2.f, 1.f, 2.f, 1.f};

#pragma unroll 1
    for (int la2 = 0; la2 < ATOMS_PER_BLK; la2++) {
        const float* S = Ssm + la2 * SSTRIDE;
        float dens = 0.f;
#pragma unroll
        for (int c = 0; c < NSYM; c++) {
            const int k = k_of[c];
            float4 s0 = *(const float4*)(S + c * NWAVE);
            float4 s1 = *(const float4*)(S + c * NWAVE + 4);
            float t = s0.x * h[k][0] + s0.y * h[k][1] + s0.z * h[k][2] + s0.w * h[k][3]
                    + s1.x * h[k][4] + s1.y * h[k][5] + s1.z * h[k][6] + s1.w * h[k][7];
            dens += wt_of[c] * t * t;
        }
        out[(blockIdx.x * ATOMS_PER_BLK + la2) * NORBIT + m] = dens;
    }
}

// ---------------------------------------------------------------------------
// Launch (2 kernels; counters self-reset inside gather)
// ---------------------------------------------------------------------------
extern "C" void kernel_launch(void* const* d_in, const int* in_sizes, int n_in,
                              void* d_out, int out_size) {
    const float* cart       = (const float*)d_in[0];
    // d_in[1] = numatoms (unused by the reference math)
    const int*   species    = (const int*)  d_in[2];
    const int*   atom_index = (const int*)  d_in[3];
    const float* shifts     = (const float*)d_in[4];
    const float* rs         = (const float*)d_in[5];
    const float* inta       = (const float*)d_in[6];
    const float* params     = (const float*)d_in[7];
    const float* hyper      = (const float*)d_in[8];
    float* out = (float*)d_out;

    pair_kernel<<<(NN + 255) / 256, 256>>>(cart, species, atom_index, shifts,
                                           rs, inta, params);
    gather_kernel<<<TOTNATOM / ATOMS_PER_BLK, 128>>>(rs, inta, params, hyper, out);
}

// round 4
// speedup vs baseline: 2.8746x; 1.1091x over previous
#include <cuda_runtime.h>

// Problem constants (fixed by the reference setup)
#define NBATCH 32
#define NATOM 256
#define PAIRS_PB 15360
#define NN (NBATCH * PAIRS_PB)      // 491520 total pairs
#define TOTNATOM (NBATCH * NATOM)   // 8192
#define NWAVE 8
#define NSYM 10                     // symmetric channels: 1, x,y,z, xx,xy,xz,yy,yz,zz
#define NORBIT 128
#define CAP 96                      // bin capacity (mean 60, sigma 7.7)
#define APB 8                       // atoms per block (gather)
#define HSTRIDE 80                  // floats per (atom,half) slab: 10*8

// Per-atom pair bins: record = {ux|sp(2 low bits), uy, uz, d} = 1 float4 (16 B)
__device__ float4 g_rec[(size_t)TOTNATOM * CAP];       // 12.6 MB (L2-resident)
__device__ int    g_cnt[TOTNATOM];                     // zero-init (.bss); gather resets
// Overflow fallback accumulator [atom][c(10)][w(8)]; gather re-zeroes on use
__device__ float4 g_S[TOTNATOM * (NSYM * NWAVE / 4)];  // 2.6 MB

__device__ __forceinline__ void red_add_v4(float4* ptr, float a, float b, float c, float d) {
    asm volatile("red.global.add.v4.f32 [%0], {%1, %2, %3, %4};"
                 :: "l"(ptr), "f"(a), "f"(b), "f"(c), "f"(d) : "memory");
}
__device__ __forceinline__ float ex2_approx(float x) {
    float r;
    asm("ex2.approx.f32 %0, %1;" : "=f"(r) : "f"(x));
    return r;
}

// ---------------------------------------------------------------------------
// Kernel 1: per-pair geometry + binning (1 int atomic + 1 STG.128 per pair)
// ---------------------------------------------------------------------------
__global__ void __launch_bounds__(256) pair_kernel(
    const float* __restrict__ cart,        // (totnatom, 3)
    const int*   __restrict__ species,     // (totnatom,)
    const int*   __restrict__ atom_index,  // (2, NN) flattened
    const float* __restrict__ shifts,      // (NN, 3)
    const float* __restrict__ rs,          // (NTYPE, 8)
    const float* __restrict__ inta,        // (NTYPE, 8)
    const float* __restrict__ params)      // (NTYPE, 8)
{
    int p = blockIdx.x * blockDim.x + threadIdx.x;
    if (p >= NN) return;

    int b = p / PAIRS_PB;
    int i = atom_index[p]      + b * NATOM;   // center (segment target)
    int j = atom_index[NN + p] + b * NATOM;   // neighbor

    // Claim slot early: the ~300-cycle atomic round-trip overlaps the math below.
    int slot = atomicAdd(&g_cnt[i], 1);

    float dx = __ldg(&cart[3 * i + 0]) - __ldg(&cart[3 * j + 0]) + __ldg(&shifts[3 * p + 0]);
    float dy = __ldg(&cart[3 * i + 1]) - __ldg(&cart[3 * j + 1]) + __ldg(&shifts[3 * p + 1]);
    float dz = __ldg(&cart[3 * i + 2]) - __ldg(&cart[3 * j + 2]) + __ldg(&shifts[3 * p + 2]);

    float d2  = dx * dx + dy * dy + dz * dz;
    float inv = rsqrtf(d2);
    float d   = d2 * inv;                 // |r|
    float ux = dx * inv, uy = dy * inv, uz = dz * inv;

    int sp = __ldg(&species[j]);

    if (slot < CAP) {
        // pack species into 2 low mantissa bits of ux (<=3 ulp perturbation)
        unsigned uxb = (__float_as_uint(ux) & ~3u) | (unsigned)sp;
        g_rec[(size_t)i * CAP + slot] = make_float4(__uint_as_float(uxb), uy, uz, d);
    } else {
        // Overflow fallback (expected never taken): exact red-atomic scatter
        float rc[NWAVE];
#pragma unroll
        for (int w = 0; w < NWAVE; w++) {
            float t = d - __ldg(&rs[sp * NWAVE + w]);
            rc[w] = __expf(__ldg(&inta[sp * NWAVE + w]) * t * t) * __ldg(&params[sp * NWAVE + w]);
        }
        float ang[NSYM] = {1.f, ux, uy, uz,
                           ux * ux, ux * uy, ux * uz, uy * uy, uy * uz, uz * uz};
        float4* Sa = g_S + (size_t)i * (NSYM * NWAVE / 4);
#pragma unroll
        for (int c = 0; c < NSYM; c++) {
            float a = ang[c];
            red_add_v4(&Sa[2 * c + 0], a * rc[0], a * rc[1], a * rc[2], a * rc[3]);
            red_add_v4(&Sa[2 * c + 1], a * rc[4], a * rc[5], a * rc[6], a * rc[7]);
        }
    }
}

// ---------------------------------------------------------------------------
// Kernel 2: gather + hyper contraction. 8 atoms/block, 128 threads, grid 1024.
// Phase 1: 16 threads/atom = (half 0/1) x (w 0..7); interleaved bin halves.
// Phase 2: combine halves in smem, folding sqrt(channel weight).
// Phase 3: thread owns orbit column m, loops 8 atoms.
// Also resets g_cnt (and g_S if overflow) for the next graph replay.
// ---------------------------------------------------------------------------
__global__ void __launch_bounds__(128) gather_kernel(
    const float* __restrict__ rs,      // (NTYPE, 8)
    const float* __restrict__ inta,    // (NTYPE, 8)
    const float* __restrict__ params,  // (NTYPE, 8)
    const float* __restrict__ hyper,   // (3, 8, 128)
    float* __restrict__ out)           // (totnatom, 128)
{
    const int tid  = threadIdx.x;
    const int la   = tid >> 4;         // local atom 0..7
    const int half = (tid >> 3) & 1;   // bin half 0/1
    const int w    = tid & 7;          // wave index 0..7
    const int a    = blockIdx.x * APB + la;

    __shared__ float Trs[32], TA[32], TP[32];            // species tables
    __shared__ float Ssm[APB * 2 * HSTRIDE];             // 5 KB

    if (tid < 32) {
        Trs[tid] = __ldg(&rs[tid]);
        TA[tid]  = __ldg(&inta[tid]) * 1.4426950408889634f;   // fold log2(e)
        TP[tid]  = __ldg(&params[tid]);
    }
    __syncthreads();

    // ---- Phase 1: per-(atom, half, w) symmetric moment accumulation ----
    const int n  = g_cnt[a];
    const int nc = min(n, CAP);
    if ((tid & 15) == 0) g_cnt[a] = 0;     // reset for next replay

    float acc[NSYM];
    if (n > CAP && half == 0) {            // overflow init + re-zero (expected never)
        float* gs = (float*)(g_S + (size_t)a * (NSYM * NWAVE / 4));
#pragma unroll
        for (int c = 0; c < NSYM; c++) {
            acc[c] = gs[c * NWAVE + w];
            gs[c * NWAVE + w] = 0.f;
        }
    } else {
#pragma unroll
        for (int c = 0; c < NSYM; c++) acc[c] = 0.f;
    }

    const float4* rec = g_rec + (size_t)a * CAP;
#pragma unroll 4
    for (int p = half; p < nc; p += 2) {
        float4 r = __ldg(&rec[p]);                 // broadcast across the 8 w-threads
        unsigned uxb = __float_as_uint(r.x);
        int sp8 = (int)(uxb & 3u) * NWAVE + w;
        float ux = __uint_as_float(uxb & ~3u);
        float t  = r.w - Trs[sp8];
        float rc = ex2_approx(TA[sp8] * t * t) * TP[sp8];

        acc[0] += rc;
        float tx = rc * ux, ty = rc * r.y, tz = rc * r.z;
        acc[1] += tx;       acc[2] += ty;       acc[3] += tz;
        acc[4] += tx * ux;  acc[5] += tx * r.y; acc[6] += tx * r.z;
        acc[7] += ty * r.y; acc[8] += ty * r.z; acc[9] += tz * r.z;
    }

    // ---- Phase 2: stash halves, then combine with sqrt(weight) fold ----
#pragma unroll
    for (int c = 0; c < NSYM; c++)
        Ssm[(la * 2 + half) * HSTRIDE + c * NWAVE + w] = acc[c];
    __syncthreads();

    {
        // channel weights {1,1,1,1,1,2,2,1,2,1} -> sqrt folded into S
        const float SQ2 = 1.41421356237309515f;
        const float scl[NSYM] = {1.f, 1.f, 1.f, 1.f, 1.f, SQ2, SQ2, 1.f, SQ2, 1.f};
#pragma unroll
        for (int idx = tid; idx < APB * HSTRIDE; idx += 128) {
            int at  = idx / HSTRIDE;
            int cw  = idx - at * HSTRIDE;
            float v = Ssm[(at * 2) * HSTRIDE + cw] + Ssm[(at * 2 + 1) * HSTRIDE + cw];
            Ssm[(at * 2) * HSTRIDE + cw] = v * scl[cw >> 3];
        }
    }
    __syncthreads();

    // ---- Phase 3: hyper contraction; thread = orbit column m ----
    const int m = tid;
    float h[3][NWAVE];
#pragma unroll
    for (int k = 0; k < 3; k++)
#pragma unroll
        for (int v = 0; v < NWAVE; v++)
            h[k][v] = __ldg(&hyper[(k * NWAVE + v) * NORBIT + m]);

    const int k_of[NSYM] = {0, 1, 1, 1, 2, 2, 2, 2, 2, 2};

#pragma unroll 1
    for (int la2 = 0; la2 < APB; la2++) {
        const float* S = Ssm + (la2 * 2) * HSTRIDE;
        float dens = 0.f;
#pragma unroll
        for (int c = 0; c < NSYM; c++) {
            const int k = k_of[c];
            float4 s0 = *(const float4*)(S + c * NWAVE);
            float4 s1 = *(const float4*)(S + c * NWAVE + 4);
            float t = s0.x * h[k][0] + s0.y * h[k][1] + s0.z * h[k][2] + s0.w * h[k][3]
                    + s1.x * h[k][4] + s1.y * h[k][5] + s1.z * h[k][6] + s1.w * h[k][7];
            dens += t * t;
        }
        out[(blockIdx.x * APB + la2) * NORBIT + m] = dens;
    }
}

// ---------------------------------------------------------------------------
// Launch (2 kernels; counters self-reset inside gather)
// ---------------------------------------------------------------------------
extern "C" void kernel_launch(void* const* d_in, const int* in_sizes, int n_in,
                              void* d_out, int out_size) {
    const float* cart       = (const float*)d_in[0];
    // d_in[1] = numatoms (unused by the reference math)
    const int*   species    = (const int*)  d_in[2];
    const int*   atom_index = (const int*)  d_in[3];
    const float* shifts     = (const float*)d_in[4];
    const float* rs         = (const float*)d_in[5];
    const float* inta       = (const float*)d_in[6];
    const float* params     = (const float*)d_in[7];
    const float* hyper      = (const float*)d_in[8];
    float* out = (float*)d_out;

    pair_kernel<<<(NN + 255) / 256, 256>>>(cart, species, atom_index, shifts,
                                           rs, inta, params);
    gather_kernel<<<TOTNATOM / APB, 128>>>(rs, inta, params, hyper, out);
}